// round 17
// baseline (speedup 1.0000x reference)
#include <cuda_runtime.h>
#include <cuda_bf16.h>
#include <cuda_fp16.h>
#include <math.h>
#include <stdint.h>

#define NPEDS_MAX 8192
#define H 256
#define E 64
#define G4 1024   // 4*H
#define KTOT 320  // E + H
#define SEQ 30
#define KT_TILES 10  // KTOT/32

// ---- device-global scratch (no allocations allowed) ----
__device__ __align__(16) __half g_h[NPEDS_MAX * H];
__device__ __align__(16) float g_c[NPEDS_MAX * H];
__device__ __align__(16) __half g_x[NPEDS_MAX * E];
__device__ __align__(16) __half g_gates[NPEDS_MAX * G4];   // fp16 gates
__device__ __align__(16) __half g_Wn[G4 * KTOT];           // [n][k] fp16
__device__ __align__(16) float g_bias[G4];

__device__ __forceinline__ float sigm(float v) { return 1.f / (1.f + __expf(-v)); }
// HW tanh (MUFU.TANH) based fast activations.
__device__ __forceinline__ float tanh_ap(float x) {
  float y;
  asm("tanh.approx.f32 %0, %1;" : "=f"(y) : "f"(x));
  return y;
}
__device__ __forceinline__ float sigm_ap(float v) {
  return fmaf(tanh_ap(0.5f * v), 0.5f, 0.5f);
}

// ---------------------------------------------------------------------------
// Init kernels (run every graph replay -> deterministic state reset)
// ---------------------------------------------------------------------------
__global__ void prep_weights(const float* __restrict__ W_ih, const float* __restrict__ W_hh,
                             const float* __restrict__ b_ih, const float* __restrict__ b_hh) {
  int idx = blockIdx.x * blockDim.x + threadIdx.x;
  if (idx < G4 * KTOT) {
    int n = idx / KTOT, k = idx - n * KTOT;
    float w = (k < E) ? W_ih[n * E + k] : W_hh[n * H + (k - E)];
    g_Wn[idx] = __float2half(w);
  }
  if (idx < G4) g_bias[idx] = b_ih[idx] + b_hh[idx];
}

__global__ void init_state(const float* __restrict__ h0, const float* __restrict__ c0, int n) {
  int idx = blockIdx.x * blockDim.x + threadIdx.x;
  if (idx < n) { g_h[idx] = __float2half(h0[idx]); g_c[idx] = c0[idx]; }
}

// embed(p) = leaky_relu( LN_2(p) @ emb_W^T + emb_b )
__global__ void embed_init(const float* __restrict__ lpr,
                           const float* __restrict__ ln1_g, const float* __restrict__ ln1_b,
                           const float* __restrict__ emb_W, const float* __restrict__ emb_b,
                           int npeds) {
  int idx = blockIdx.x * blockDim.x + threadIdx.x;
  if (idx >= npeds * E) return;
  int ped = idx / E, j = idx - ped * E;
  float a = lpr[ped * 2 + 0], b = lpr[ped * 2 + 1];
  float d = 0.5f * (a - b);
  float inv = rsqrtf(d * d + 1e-5f);
  float na =  d * inv * ln1_g[0] + ln1_b[0];
  float nb = -d * inv * ln1_g[1] + ln1_b[1];
  float y = na * emb_W[j * 2 + 0] + nb * emb_W[j * 2 + 1] + emb_b[j];
  g_x[idx] = __float2half((y > 0.f) ? y : 0.01f * y);
}

// ---------------------------------------------------------------------------
// Per-step GEMM (fp16 MMA/accum, ldmatrix, 3-stage cp.async, tiny CTAs):
//   g_gates[M,1024](fp16) = [x|h][M,320] @ Wn^T
// BM=64, BN=64, BK=32. 128 threads = 4 warps (2m x 2n), warp tile 32x32.
// grid = 16 x 128 = 2048 CTAs; 6 CTAs/SM -> 24 warps/SM.
// ---------------------------------------------------------------------------
#define A_TILE_U 1280               // 64*20 uint32
#define STAGE_B 5120                // bytes per tile (A or B)
#define SMEM_BYTES (6 * STAGE_B)    // 30720

__global__ __launch_bounds__(128, 6) void gates_gemm(int npeds) {
  extern __shared__ __align__(16) uint32_t smem[];
  uint32_t* const As0 = smem;                   // [3][64][20]
  uint32_t* const Bs0 = smem + 3 * A_TILE_U;    // [3][64][20]

  const int bm = blockIdx.y * 64;
  const int bn = blockIdx.x * 64;
  const int t = threadIdx.x;
  const int warp = t >> 5;
  const int lane = t & 31;
  const int wm = (warp >> 1) * 32;   // 0 | 32
  const int wn = (warp & 1) * 32;    // 0 | 32
  const int gr = lane >> 2;   // 0..7  (store epilogue)
  const int lc = lane & 3;    // 0..3

  const int lg = lane >> 3;       // lane group 0..3
  const int lr = lane & 7;        // row within group
  const uint32_t aLane = (uint32_t)__cvta_generic_to_shared(
      &As0[(wm + (lg & 1) * 8 + lr) * 20 + (lg >> 1) * 4]);
  const uint32_t bLane = (uint32_t)__cvta_generic_to_shared(
      &Bs0[(wn + (lg >> 1) * 8 + lr) * 20 + (lg & 1) * 4]);

  uint32_t acc[2][4][2];          // f16x2 accumulators (16 regs)
#pragma unroll
  for (int i = 0; i < 2; ++i)
#pragma unroll
    for (int j = 0; j < 4; ++j) { acc[i][j][0] = 0u; acc[i][j][1] = 0u; }

  auto load_tile = [&](int kt, int stage) {
    const int k0 = kt * 32;
    const __half* srcA;
    int ldk, koff;
    if (k0 < E) { srcA = g_x; ldk = E; koff = k0; }
    else        { srcA = g_h; ldk = H; koff = k0 - E; }
    // A and B: 64 rows x 4 chunks = 256 chunks each, 2 per thread
#pragma unroll
    for (int r = 0; r < 2; ++r) {
      const int idx = t + r * 128;
      const int row = idx >> 2, c = idx & 3;
      const void* gA = srcA + (size_t)(bm + row) * ldk + koff + c * 8;
      uint32_t dA = (uint32_t)__cvta_generic_to_shared(
          &As0[stage * A_TILE_U + row * 20 + c * 4]);
      asm volatile("cp.async.cg.shared.global [%0], [%1], 16;\n" :: "r"(dA), "l"(gA));
      const void* gB = g_Wn + (size_t)(bn + row) * KTOT + k0 + c * 8;
      uint32_t dB = (uint32_t)__cvta_generic_to_shared(
          &Bs0[stage * A_TILE_U + row * 20 + c * 4]);
      asm volatile("cp.async.cg.shared.global [%0], [%1], 16;\n" :: "r"(dB), "l"(gB));
    }
    asm volatile("cp.async.commit_group;\n");
  };

  load_tile(0, 0);
  load_tile(1, 1);

#pragma unroll
  for (int kt = 0; kt < KT_TILES; ++kt) {
    if (kt + 1 < KT_TILES)
      asm volatile("cp.async.wait_group 1;\n" ::: "memory");
    else
      asm volatile("cp.async.wait_group 0;\n" ::: "memory");
    __syncthreads();
    if (kt + 2 < KT_TILES) load_tile(kt + 2, (kt + 2) % 3);

    const int stage = kt % 3;
    const uint32_t aSt = aLane + (uint32_t)stage * STAGE_B;
    const uint32_t bSt = bLane + (uint32_t)stage * STAGE_B;

#pragma unroll
    for (int ks = 0; ks < 2; ++ks) {
      const uint32_t kOff = (uint32_t)ks * 32u;
      uint32_t a[2][4], b[4][2];
#pragma unroll
      for (int mt = 0; mt < 2; ++mt) {
        asm volatile(
          "ldmatrix.sync.aligned.m8n8.x4.shared.b16 {%0,%1,%2,%3}, [%4];"
          : "=r"(a[mt][0]), "=r"(a[mt][1]), "=r"(a[mt][2]), "=r"(a[mt][3])
          : "r"(aSt + kOff + (uint32_t)mt * 1280u));   // 16 rows * 80B
      }
#pragma unroll
      for (int p = 0; p < 2; ++p) {
        asm volatile(
          "ldmatrix.sync.aligned.m8n8.x4.shared.b16 {%0,%1,%2,%3}, [%4];"
          : "=r"(b[2 * p][0]), "=r"(b[2 * p][1]),
            "=r"(b[2 * p + 1][0]), "=r"(b[2 * p + 1][1])
          : "r"(bSt + kOff + (uint32_t)p * 1280u));
      }
#pragma unroll
      for (int mt = 0; mt < 2; ++mt)
#pragma unroll
        for (int nt = 0; nt < 4; ++nt) {
          asm volatile(
            "mma.sync.aligned.m16n8k16.row.col.f16.f16.f16.f16 "
            "{%0,%1}, {%2,%3,%4,%5}, {%6,%7}, {%0,%1};"
            : "+r"(acc[mt][nt][0]), "+r"(acc[mt][nt][1])
            : "r"(a[mt][0]), "r"(a[mt][1]), "r"(a[mt][2]), "r"(a[mt][3]),
              "r"(b[nt][0]), "r"(b[nt][1]));
        }
    }
  }

  // ---- epilogue: accumulators ARE the fp16 gates; direct stores ----
#pragma unroll
  for (int mt = 0; mt < 2; ++mt) {
    const int row = bm + wm + mt * 16 + gr;
#pragma unroll
    for (int nt = 0; nt < 4; ++nt) {
      const int col = bn + wn + nt * 8 + lc * 2;
      *(uint32_t*)(g_gates + (size_t)row * G4 + col) = acc[mt][nt][0];
      *(uint32_t*)(g_gates + (size_t)(row + 8) * G4 + col) = acc[mt][nt][1];
    }
  }
}

// ---------------------------------------------------------------------------
// Fused per-step tail: LSTM elementwise + LN2 + pos projection (rel out) +
// embed(rel) -> next x. Channel-pair lanes -> all accesses 128B/warp.
// All LSTM activations via MUFU.TANH (5 MUFU/cell).
// ---------------------------------------------------------------------------
__global__ __launch_bounds__(256) void lstm_fused(
    const float* __restrict__ ln2_g, const float* __restrict__ ln2_b,
    const float* __restrict__ pos_W, const float* __restrict__ pos_b,
    const float* __restrict__ emb_W, const float* __restrict__ emb_b,
    const float* __restrict__ ln1_g, const float* __restrict__ ln1_b,
    float* __restrict__ rel_out, int npeds) {
  const int warp = threadIdx.x >> 5;
  const int lane = threadIdx.x & 31;
  const int ped = blockIdx.x * 8 + warp;
  if (ped >= npeds) return;

  const __half2* gp2 = (const __half2*)g_gates + (size_t)ped * (G4 / 2);
  float* cp = g_c + (size_t)ped * H;
  __half* hp = g_h + (size_t)ped * H;

  float hn[8];
  float s = 0.f, ss = 0.f;
#pragma unroll
  for (int j = 0; j < 4; ++j) {
    const int p2 = lane + j * 32;          // half2 index within a gate block
    const int ch = p2 * 2;                 // even channel
    const float2 gi = __half22float2(gp2[p2]);
    const float2 gf = __half22float2(gp2[128 + p2]);
    const float2 gg = __half22float2(gp2[256 + p2]);
    const float2 go = __half22float2(gp2[384 + p2]);
    const float2 bi = *(const float2*)&g_bias[ch];
    const float2 bf = *(const float2*)&g_bias[256 + ch];
    const float2 bg = *(const float2*)&g_bias[512 + ch];
    const float2 bo = *(const float2*)&g_bias[768 + ch];
    const float2 cv = *(const float2*)&cp[ch];

    const float cn0 = sigm_ap(gf.x + bf.x) * cv.x + sigm_ap(gi.x + bi.x) * tanh_ap(gg.x + bg.x);
    const float cn1 = sigm_ap(gf.y + bf.y) * cv.y + sigm_ap(gi.y + bi.y) * tanh_ap(gg.y + bg.y);
    const float hv0 = sigm_ap(go.x + bo.x) * tanh_ap(cn0);
    const float hv1 = sigm_ap(go.y + bo.y) * tanh_ap(cn1);
    *(float2*)&cp[ch] = make_float2(cn0, cn1);
    *(__half2*)&hp[ch] = __floats2half2_rn(hv0, hv1);
    hn[j * 2] = hv0; hn[j * 2 + 1] = hv1;
    s += hv0 + hv1;
    ss += hv0 * hv0 + hv1 * hv1;
  }
#pragma unroll
  for (int o = 16; o > 0; o >>= 1) {
    s += __shfl_xor_sync(0xffffffffu, s, o);
    ss += __shfl_xor_sync(0xffffffffu, ss, o);
  }
  const float mu = s * (1.f / 256.f);
  const float var = ss * (1.f / 256.f) - mu * mu;
  const float rstd = rsqrtf(var + 1e-5f);

  float d0 = 0.f, d1 = 0.f;
#pragma unroll
  for (int j = 0; j < 4; ++j) {
    const int ch = lane * 2 + j * 64;
    const float2 g2 = *(const float2*)&ln2_g[ch];
    const float2 b2 = *(const float2*)&ln2_b[ch];
    const float2 w0 = *(const float2*)&pos_W[ch];
    const float2 w1 = *(const float2*)&pos_W[256 + ch];
    const float nh0 = (hn[j * 2] - mu) * rstd * g2.x + b2.x;
    const float nh1 = (hn[j * 2 + 1] - mu) * rstd * g2.y + b2.y;
    d0 += nh0 * w0.x + nh1 * w0.y;
    d1 += nh0 * w1.x + nh1 * w1.y;
  }
#pragma unroll
  for (int o = 16; o > 0; o >>= 1) {
    d0 += __shfl_xor_sync(0xffffffffu, d0, o);
    d1 += __shfl_xor_sync(0xffffffffu, d1, o);
  }
  const float r0 = sigm(d0 + pos_b[0]);
  const float r1 = sigm(d1 + pos_b[1]);
  if (lane == 0) {
    rel_out[(size_t)ped * 2 + 0] = r0;
    rel_out[(size_t)ped * 2 + 1] = r1;
  }

  // embed(rel) -> next x  (LN over 2 elems)
  const float d = 0.5f * (r0 - r1);
  const float inv = rsqrtf(d * d + 1e-5f);
  const float na =  d * inv * ln1_g[0] + ln1_b[0];
  const float nb = -d * inv * ln1_g[1] + ln1_b[1];
  __half* xp = g_x + (size_t)ped * E;
#pragma unroll
  for (int q = 0; q < 2; ++q) {
    const int j = lane * 2 + q;
    const float y = na * emb_W[j * 2 + 0] + nb * emb_W[j * 2 + 1] + emb_b[j];
    xp[j] = __float2half((y > 0.f) ? y : 0.01f * y);
  }
}

// ---------------------------------------------------------------------------
extern "C" void kernel_launch(void* const* d_in, const int* in_sizes, int n_in,
                              void* d_out, int out_size) {
  const float* last_pos_rel = (const float*)d_in[1];
  const float* h0   = (const float*)d_in[2];
  const float* c0   = (const float*)d_in[3];
  const float* W_ih = (const float*)d_in[4];
  const float* W_hh = (const float*)d_in[5];
  const float* b_ih = (const float*)d_in[6];
  const float* b_hh = (const float*)d_in[7];
  const float* emb_W = (const float*)d_in[8];
  const float* emb_b = (const float*)d_in[9];
  const float* ln1_g = (const float*)d_in[10];
  const float* ln1_b = (const float*)d_in[11];
  const float* pos_W = (const float*)d_in[12];
  const float* pos_b = (const float*)d_in[13];
  const float* ln2_g = (const float*)d_in[14];
  const float* ln2_b = (const float*)d_in[15];
  float* out = (float*)d_out;

  const int npeds = in_sizes[0] / 2;  // 8192

  static int smem_set = 0;
  if (!smem_set) {
    cudaFuncSetAttribute(gates_gemm, cudaFuncAttributeMaxDynamicSharedMemorySize,
                         SMEM_BYTES);
    smem_set = 1;
  }

  prep_weights<<<(G4 * KTOT + 255) / 256, 256>>>(W_ih, W_hh, b_ih, b_hh);
  init_state<<<(npeds * H + 255) / 256, 256>>>(h0, c0, npeds * H);
  embed_init<<<(npeds * E + 255) / 256, 256>>>(last_pos_rel, ln1_g, ln1_b, emb_W, emb_b, npeds);

  dim3 ggrid(G4 / 64, npeds / 64);   // 16 x 128 = 2048 CTAs
  for (int s = 0; s < SEQ; ++s) {
    gates_gemm<<<ggrid, 128, SMEM_BYTES>>>(npeds);
    lstm_fused<<<npeds / 8, 256>>>(ln2_g, ln2_b, pos_W, pos_b, emb_W, emb_b,
                                   ln1_g, ln1_b, out + (size_t)s * npeds * 2, npeds);
  }
}